// round 1
// baseline (speedup 1.0000x reference)
#include <cuda_runtime.h>
#include <cstdint>
#include <cstddef>

#define BB 32
#define N1 2048
#define S1 512
#define S2 256
#define NS 32
#define R2C 0.25f
#define NSLOT 64
#define CMAX 256

// ---------------- static device buffers (no allocation allowed) ----------------
__device__ float g_F0[(size_t)BB*64*N1];        // conv1 raw
__device__ float g_F1[(size_t)BB*64*N1];        // conv2 raw
__device__ float g_nx1[(size_t)BB*S1*3];
__device__ int   g_fps1[BB*S1];
__device__ int   g_gi1[(size_t)BB*S1*NS];
__device__ float g_G1[(size_t)BB*S1*128*NS];    // sg1a raw (256MB)
__device__ float g_F1max[(size_t)BB*S1*128];
__device__ float g_nx2[(size_t)BB*S2*3];
__device__ int   g_fps2[BB*S2];
__device__ int   g_gi2[(size_t)BB*S2*NS];
__device__ float g_G2[(size_t)BB*S2*256*NS];    // sg2a raw (256MB)
__device__ float g_F2max[(size_t)BB*S2*256];

__device__ double g_psum[6*NSLOT*CMAX];
__device__ double g_psq [6*NSLOT*CMAX];
__device__ float  g_scale[6*CMAX];
__device__ float  g_bias [6*CMAX];

// ---------------- BN finalize ----------------
__global__ void k_fin(const double* __restrict__ psum, const double* __restrict__ psq,
                      float* __restrict__ sc, float* __restrict__ bi, int C, double invM)
{
    int t = threadIdx.x;
    if (t >= C) return;
    double s = 0.0, q = 0.0;
    for (int k = 0; k < NSLOT; k++) { s += psum[k*CMAX + t]; q += psq[k*CMAX + t]; }
    double mean = s * invM;
    double var  = q * invM - mean * mean;
    if (var < 0.0) var = 0.0;
    double sv = 1.0 / sqrt(var + 1e-5);
    sc[t] = (float)sv;
    bi[t] = (float)(-mean * sv);
}

// ---------------- conv1: [64,3] x [B,3,N] ----------------
__global__ void k_conv1(const float* __restrict__ x, const float* __restrict__ W,
                        float* __restrict__ F0, double* __restrict__ psum, double* __restrict__ psq)
{
    int c = blockIdx.x, b = blockIdx.y, t = threadIdx.x;
    float w0 = W[c*3], w1 = W[c*3+1], w2 = W[c*3+2];
    const float* xb = x + (size_t)b*3*N1;
    float* o = F0 + ((size_t)b*64 + c)*N1;
    float ls = 0.f, lq = 0.f;
    for (int n = t; n < N1; n += 256) {
        float v = w0*xb[n] + w1*xb[N1+n] + w2*xb[2*N1+n];
        o[n] = v; ls += v; lq += v*v;
    }
    for (int off = 16; off; off >>= 1) {
        ls += __shfl_down_sync(0xffffffffu, ls, off);
        lq += __shfl_down_sync(0xffffffffu, lq, off);
    }
    __shared__ float ws_[8], wq_[8];
    if ((t & 31) == 0) { ws_[t >> 5] = ls; wq_[t >> 5] = lq; }
    __syncthreads();
    if (t == 0) {
        float S = 0.f, Q = 0.f;
        for (int i = 0; i < 8; i++) { S += ws_[i]; Q += wq_[i]; }
        atomicAdd(&psum[(b & (NSLOT-1))*CMAX + c], (double)S);
        atomicAdd(&psq [(b & (NSLOT-1))*CMAX + c], (double)Q);
    }
}

// ---------------- conv2: [64,64] x relu(bn(F0)) ----------------
__global__ void k_conv2(const float* __restrict__ F0, const float* __restrict__ W,
                        const float* __restrict__ sc0, const float* __restrict__ bi0,
                        float* __restrict__ F1, double* __restrict__ psum, double* __restrict__ psq)
{
    __shared__ float in_t[64*64];
    __shared__ float ws[64*65];
    __shared__ float pspart[4*64], pqpart[4*64];
    int tile = blockIdx.x, b = blockIdx.y, t = threadIdx.x;
    for (int i = t; i < 4096; i += 256) { int c = i >> 6, k = i & 63; ws[c*65 + k] = W[i]; }
    const float* F0b = F0 + (size_t)b*64*N1 + tile*64;
    for (int i = t; i < 4096; i += 256) {
        int k = i >> 6, nn = i & 63;
        float v = F0b[(size_t)k*N1 + nn]*sc0[k] + bi0[k];
        in_t[k*64 + nn] = fmaxf(v, 0.f);
    }
    __syncthreads();
    int c = t & 63, nq = t >> 6;
    float acc[16];
    #pragma unroll
    for (int j = 0; j < 16; j++) acc[j] = 0.f;
    for (int k = 0; k < 64; k++) {
        float wv = ws[c*65 + k];
        const float* ar = &in_t[k*64 + nq*16];
        #pragma unroll
        for (int jq = 0; jq < 4; jq++) {
            float4 a = *(const float4*)(ar + 4*jq);
            acc[4*jq+0] += wv*a.x; acc[4*jq+1] += wv*a.y;
            acc[4*jq+2] += wv*a.z; acc[4*jq+3] += wv*a.w;
        }
    }
    float lsum = 0.f, lsq = 0.f;
    float* F1b = F1 + ((size_t)b*64 + c)*N1 + tile*64 + nq*16;
    #pragma unroll
    for (int j = 0; j < 16; j++) { float v = acc[j]; F1b[j] = v; lsum += v; lsq += v*v; }
    pspart[nq*64 + c] = lsum; pqpart[nq*64 + c] = lsq;
    __syncthreads();
    if (t < 64) {
        float s = pspart[t] + pspart[64+t] + pspart[128+t] + pspart[192+t];
        float q = pqpart[t] + pqpart[64+t] + pqpart[128+t] + pqpart[192+t];
        int slot = (blockIdx.x + 32*blockIdx.y) & (NSLOT-1);
        atomicAdd(&psum[slot*CMAX + t], (double)s);
        atomicAdd(&psq [slot*CMAX + t], (double)q);
    }
}

// ---------------- FPS (exact fp match with reference) ----------------
template<int N, int S>
__global__ void k_fps(const float* __restrict__ P, size_t bstride, size_t pstride, size_t cstride,
                      int* __restrict__ outIdx, float* __restrict__ outXYZ)
{
    int b = blockIdx.x, t = threadIdx.x;
    const float* Pb = P + (size_t)b*bstride;
    __shared__ float dist[N];
    __shared__ float rv[256];
    __shared__ int   ri[256];
    __shared__ int   sfar;
    for (int j = t; j < N; j += 256) dist[j] = 1e10f;
    if (t == 0) sfar = 0;
    __syncthreads();
    for (int s = 0; s < S; s++) {
        int far = sfar;
        float fx = Pb[(size_t)far*pstride];
        float fy = Pb[(size_t)far*pstride + cstride];
        float fz = Pb[(size_t)far*pstride + 2*cstride];
        if (t == 0) {
            outIdx[(size_t)b*S + s] = far;
            float* o = &outXYZ[((size_t)b*S + s)*3];
            o[0] = fx; o[1] = fy; o[2] = fz;
        }
        float bv = -1.f; int bi = N;
        for (int j = t; j < N; j += 256) {
            float dx = __fsub_rn(Pb[(size_t)j*pstride], fx);
            float dy = __fsub_rn(Pb[(size_t)j*pstride + cstride], fy);
            float dz = __fsub_rn(Pb[(size_t)j*pstride + 2*cstride], fz);
            float d = __fadd_rn(__fadd_rn(__fmul_rn(dx,dx), __fmul_rn(dy,dy)), __fmul_rn(dz,dz));
            float nd = fminf(dist[j], d);
            dist[j] = nd;
            if (nd > bv) { bv = nd; bi = j; }
        }
        rv[t] = bv; ri[t] = bi;
        __syncthreads();
        for (int off = 128; off > 0; off >>= 1) {
            if (t < off) {
                float v2 = rv[t+off]; int i2 = ri[t+off];
                if (v2 > rv[t] || (v2 == rv[t] && i2 < ri[t])) { rv[t] = v2; ri[t] = i2; }
            }
            __syncthreads();
        }
        if (t == 0) sfar = ri[0];
        __syncthreads();
    }
}

// ---------------- ball query: first NS ascending indices with d<=R2 ----------------
__global__ void k_ball(const float* __restrict__ C, size_t bstrideC, size_t pstride, size_t cstride,
                       int N, const float* __restrict__ Q, int S, int* __restrict__ gi)
{
    int wid = threadIdx.x >> 5, lane = threadIdx.x & 31;
    int g = blockIdx.x*4 + wid;
    int b = g / S;
    const float* Cb = C + (size_t)b*bstrideC;
    const float* q = Q + (size_t)g*3;
    float qx = q[0], qy = q[1], qz = q[2];
    __shared__ int buf[4][NS];
    int cnt = 0;
    for (int base = 0; base < N && cnt < NS; base += 32) {
        int j = base + lane;
        float dx = __fsub_rn(Cb[(size_t)j*pstride], qx);
        float dy = __fsub_rn(Cb[(size_t)j*pstride + cstride], qy);
        float dz = __fsub_rn(Cb[(size_t)j*pstride + 2*cstride], qz);
        float d = __fadd_rn(__fadd_rn(__fmul_rn(dx,dx), __fmul_rn(dy,dy)), __fmul_rn(dz,dz));
        bool ok = !(d > R2C);
        unsigned m = __ballot_sync(0xffffffffu, ok);
        int pos = cnt + __popc(m & ((1u << lane) - 1u));
        if (ok && pos < NS) buf[wid][pos] = j;
        cnt += __popc(m);
    }
    __syncwarp();
    int first = buf[wid][0];
    int mm = cnt < NS ? cnt : NS;
    int v = (lane < mm) ? buf[wid][lane] : first;
    gi[(size_t)g*NS + lane] = v;
}

// ---------------- SG "a": gather + center/concat + GEMM, store raw + sums ----------------
template<int CIN, int COUT>
__global__ void k_sg_gather(const float* __restrict__ W,
                            const float* __restrict__ Fsrc, size_t sb, size_t sn, size_t sc,
                            const float* __restrict__ fscale, const float* __restrict__ fbias,
                            const int* __restrict__ gi, const int* __restrict__ fpsidx, int S,
                            float* __restrict__ G,
                            double* __restrict__ psum, double* __restrict__ psq)
{
    constexpr int CH = CIN/2;
    constexpr int WPAD = COUT + 4;
    extern __shared__ float sm[];
    float* agg = sm;                         // CIN*NS
    float* wT  = agg + CIN*NS;               // 32*WPAD
    float* fc  = wT + 32*WPAD;               // CH
    float* ps  = fc + CH;                    // 4*COUT
    float* pq  = ps + 4*COUT;                // 4*COUT
    int*   gix = (int*)(pq + 4*COUT);        // 32

    int g = blockIdx.x;
    int b = g / S, s = g % S;
    int t = threadIdx.x;                     // COUT threads
    const float* Fb = Fsrc + (size_t)b*sb;

    if (t < 32) gix[t] = gi[(size_t)g*NS + t];
    if (t < CH) {
        int ci = fpsidx[(size_t)b*S + s];
        float v = Fb[(size_t)ci*sn + (size_t)t*sc]*fscale[t] + fbias[t];
        fc[t] = fmaxf(v, 0.f);
    }
    __syncthreads();
    for (int i = t; i < CH*NS; i += COUT) {
        int c = i % CH, k = i / CH;
        int idx = gix[k];
        float v = Fb[(size_t)idx*sn + (size_t)c*sc]*fscale[c] + fbias[c];
        v = fmaxf(v, 0.f);
        agg[c*NS + k]      = v - fc[c];
        agg[(c+CH)*NS + k] = fc[c];
    }

    constexpr int NC4 = COUT/4;
    int c4 = (t % NC4)*4;
    int sq = t / NC4;
    float acc[4][8];
    #pragma unroll
    for (int a = 0; a < 4; a++)
        #pragma unroll
        for (int c2 = 0; c2 < 8; c2++) acc[a][c2] = 0.f;

    for (int ch = 0; ch < CIN/32; ch++) {
        __syncthreads();
        for (int i = t; i < COUT*32; i += COUT) {
            int c = i >> 5, kk = i & 31;
            wT[kk*WPAD + c] = W[(size_t)c*CIN + ch*32 + kk];
        }
        __syncthreads();
        #pragma unroll
        for (int kk = 0; kk < 32; kk++) {
            float4 wv = *(const float4*)&wT[kk*WPAD + c4];
            float4 a0 = *(const float4*)&agg[(ch*32+kk)*NS + sq*8];
            float4 a1 = *(const float4*)&agg[(ch*32+kk)*NS + sq*8 + 4];
            float w4[4] = {wv.x, wv.y, wv.z, wv.w};
            float av[8] = {a0.x, a0.y, a0.z, a0.w, a1.x, a1.y, a1.z, a1.w};
            #pragma unroll
            for (int ci = 0; ci < 4; ci++)
                #pragma unroll
                for (int sj = 0; sj < 8; sj++)
                    acc[ci][sj] += w4[ci]*av[sj];
        }
    }

    float* Gg = G + (size_t)g*COUT*NS;
    #pragma unroll
    for (int ci = 0; ci < 4; ci++) {
        int row = c4 + ci;
        float lsum = 0.f, lsq = 0.f;
        #pragma unroll
        for (int sj = 0; sj < 8; sj++) { float v = acc[ci][sj]; lsum += v; lsq += v*v; }
        *(float4*)&Gg[row*NS + sq*8]     = make_float4(acc[ci][0], acc[ci][1], acc[ci][2], acc[ci][3]);
        *(float4*)&Gg[row*NS + sq*8 + 4] = make_float4(acc[ci][4], acc[ci][5], acc[ci][6], acc[ci][7]);
        ps[sq*COUT + row] = lsum; pq[sq*COUT + row] = lsq;
    }
    __syncthreads();
    float s0 = ps[t] + ps[COUT+t] + ps[2*COUT+t] + ps[3*COUT+t];
    float q0 = pq[t] + pq[COUT+t] + pq[2*COUT+t] + pq[3*COUT+t];
    int slot = g & (NSLOT-1);
    atomicAdd(&psum[slot*CMAX + t], (double)s0);
    atomicAdd(&psq [slot*CMAX + t], (double)q0);
}

// ---------------- SG "b": bn+relu input, GEMM, row-max + sums only ----------------
template<int C>
__global__ void k_sg_bngemm(const float* __restrict__ W, const float* __restrict__ Graw,
                            const float* __restrict__ insc, const float* __restrict__ inb,
                            float* __restrict__ Fmax,
                            double* __restrict__ psum, double* __restrict__ psq)
{
    constexpr int WPAD = C + 4;
    extern __shared__ float sm[];
    float* agg = sm;                 // C*NS
    float* wT  = agg + C*NS;         // 32*WPAD
    float* ps  = wT + 32*WPAD;       // 4*C
    float* pq  = ps + 4*C;           // 4*C
    float* pm  = pq + 4*C;           // 4*C

    int g = blockIdx.x, t = threadIdx.x;    // C threads
    const float* Gg = Graw + (size_t)g*C*NS;
    for (int i = t; i < C*NS; i += C) {
        int c = i >> 5;
        float v = Gg[i]*insc[c] + inb[c];
        agg[i] = fmaxf(v, 0.f);
    }

    constexpr int NC4 = C/4;
    int c4 = (t % NC4)*4;
    int sq = t / NC4;
    float acc[4][8];
    #pragma unroll
    for (int a = 0; a < 4; a++)
        #pragma unroll
        for (int c2 = 0; c2 < 8; c2++) acc[a][c2] = 0.f;

    for (int ch = 0; ch < C/32; ch++) {
        __syncthreads();
        for (int i = t; i < C*32; i += C) {
            int c = i >> 5, kk = i & 31;
            wT[kk*WPAD + c] = W[(size_t)c*C + ch*32 + kk];
        }
        __syncthreads();
        #pragma unroll
        for (int kk = 0; kk < 32; kk++) {
            float4 wv = *(const float4*)&wT[kk*WPAD + c4];
            float4 a0 = *(const float4*)&agg[(ch*32+kk)*NS + sq*8];
            float4 a1 = *(const float4*)&agg[(ch*32+kk)*NS + sq*8 + 4];
            float w4[4] = {wv.x, wv.y, wv.z, wv.w};
            float av[8] = {a0.x, a0.y, a0.z, a0.w, a1.x, a1.y, a1.z, a1.w};
            #pragma unroll
            for (int ci = 0; ci < 4; ci++)
                #pragma unroll
                for (int sj = 0; sj < 8; sj++)
                    acc[ci][sj] += w4[ci]*av[sj];
        }
    }

    #pragma unroll
    for (int ci = 0; ci < 4; ci++) {
        int row = c4 + ci;
        float lsum = 0.f, lsq = 0.f, lmax = -3.4e38f;
        #pragma unroll
        for (int sj = 0; sj < 8; sj++) {
            float v = acc[ci][sj];
            lsum += v; lsq += v*v; lmax = fmaxf(lmax, v);
        }
        ps[sq*C + row] = lsum; pq[sq*C + row] = lsq; pm[sq*C + row] = lmax;
    }
    __syncthreads();
    float s0 = ps[t] + ps[C+t] + ps[2*C+t] + ps[3*C+t];
    float q0 = pq[t] + pq[C+t] + pq[2*C+t] + pq[3*C+t];
    float m0 = fmaxf(fmaxf(pm[t], pm[C+t]), fmaxf(pm[2*C+t], pm[3*C+t]));
    Fmax[(size_t)g*C + t] = m0;
    int slot = g & (NSLOT-1);
    atomicAdd(&psum[slot*CMAX + t], (double)s0);
    atomicAdd(&psq [slot*CMAX + t], (double)q0);
}

// ---------------- final output f2 ----------------
__global__ void k_out_f2(const float* __restrict__ Fmax, const float* __restrict__ sc,
                         const float* __restrict__ bi, float* __restrict__ out)
{
    size_t i = (size_t)blockIdx.x*256 + threadIdx.x;   // 32*256*256
    int s = i & 255;
    size_t r = i >> 8;
    int c = r & 255;
    int b = (int)(r >> 8);
    float v = Fmax[((size_t)(b*256 + s))*256 + c]*sc[c] + bi[c];
    out[24576 + i] = fmaxf(v, 0.f);
}

// ---------------- launch ----------------
extern "C" void kernel_launch(void* const* d_in, const int* in_sizes, int n_in,
                              void* d_out, int out_size)
{
    const float* x  = (const float*)d_in[0];
    const float* w1 = (const float*)d_in[1];
    const float* w2 = (const float*)d_in[2];
    const float* wa = (const float*)d_in[3];
    const float* wb = (const float*)d_in[4];
    const float* wc = (const float*)d_in[5];
    const float* wd = (const float*)d_in[6];

    void *pF0, *pF1, *pnx1, *pfps1, *pgi1, *pG1, *pF1max;
    void *pnx2, *pfps2, *pgi2, *pG2, *pF2max, *ppsum, *ppsq, *pscale, *pbias;
    cudaGetSymbolAddress(&pF0, g_F0);       cudaGetSymbolAddress(&pF1, g_F1);
    cudaGetSymbolAddress(&pnx1, g_nx1);     cudaGetSymbolAddress(&pfps1, g_fps1);
    cudaGetSymbolAddress(&pgi1, g_gi1);     cudaGetSymbolAddress(&pG1, g_G1);
    cudaGetSymbolAddress(&pF1max, g_F1max); cudaGetSymbolAddress(&pnx2, g_nx2);
    cudaGetSymbolAddress(&pfps2, g_fps2);   cudaGetSymbolAddress(&pgi2, g_gi2);
    cudaGetSymbolAddress(&pG2, g_G2);       cudaGetSymbolAddress(&pF2max, g_F2max);
    cudaGetSymbolAddress(&ppsum, g_psum);   cudaGetSymbolAddress(&ppsq, g_psq);
    cudaGetSymbolAddress(&pscale, g_scale); cudaGetSymbolAddress(&pbias, g_bias);

    double* psum = (double*)ppsum;
    double* psq  = (double*)ppsq;
    float* scl   = (float*)pscale;
    float* bia   = (float*)pbias;

    const int smA1 = (128*NS + 32*(128+4) + 64  + 8*128)*4 + 32*4;
    const int smA2 = (256*NS + 32*(256+4) + 128 + 8*256)*4 + 32*4;
    const int smB1 = (128*NS + 32*(128+4) + 12*128)*4;
    const int smB2 = (256*NS + 32*(256+4) + 12*256)*4;
    cudaFuncSetAttribute(k_sg_gather<256,256>, cudaFuncAttributeMaxDynamicSharedMemorySize, smA2);
    cudaFuncSetAttribute(k_sg_bngemm<256>,     cudaFuncAttributeMaxDynamicSharedMemorySize, smB2);

    cudaMemsetAsync(psum, 0, 6*NSLOT*CMAX*sizeof(double), 0);
    cudaMemsetAsync(psq,  0, 6*NSLOT*CMAX*sizeof(double), 0);

    // stage 0: convs + BN
    k_conv1<<<dim3(64,BB), 256>>>(x, w1, (float*)pF0, psum + 0*NSLOT*CMAX, psq + 0*NSLOT*CMAX);
    k_fin<<<1,64>>>(psum + 0*NSLOT*CMAX, psq + 0*NSLOT*CMAX, scl + 0*CMAX, bia + 0*CMAX, 64, 1.0/((double)BB*N1));
    k_conv2<<<dim3(32,BB), 256>>>((const float*)pF0, w2, scl + 0*CMAX, bia + 0*CMAX,
                                  (float*)pF1, psum + 1*NSLOT*CMAX, psq + 1*NSLOT*CMAX);
    k_fin<<<1,64>>>(psum + 1*NSLOT*CMAX, psq + 1*NSLOT*CMAX, scl + 1*CMAX, bia + 1*CMAX, 64, 1.0/((double)BB*N1));

    // stage 1: FPS + ball on raw coords
    k_fps<N1,S1><<<BB,256>>>(x, (size_t)3*N1, 1, N1, (int*)pfps1, (float*)pnx1);
    k_ball<<<BB*S1/4,128>>>(x, (size_t)3*N1, 1, N1, N1, (const float*)pnx1, S1, (int*)pgi1);

    // sg1
    k_sg_gather<128,128><<<BB*S1, 128, smA1>>>(wa, (const float*)pF1, (size_t)64*N1, 1, N1,
        scl + 1*CMAX, bia + 1*CMAX, (const int*)pgi1, (const int*)pfps1, S1,
        (float*)pG1, psum + 2*NSLOT*CMAX, psq + 2*NSLOT*CMAX);
    k_fin<<<1,128>>>(psum + 2*NSLOT*CMAX, psq + 2*NSLOT*CMAX, scl + 2*CMAX, bia + 2*CMAX, 128, 1.0/((double)BB*S1*NS));
    k_sg_bngemm<128><<<BB*S1, 128, smB1>>>(wb, (const float*)pG1, scl + 2*CMAX, bia + 2*CMAX,
        (float*)pF1max, psum + 3*NSLOT*CMAX, psq + 3*NSLOT*CMAX);
    k_fin<<<1,128>>>(psum + 3*NSLOT*CMAX, psq + 3*NSLOT*CMAX, scl + 3*CMAX, bia + 3*CMAX, 128, 1.0/((double)BB*S1*NS));

    // stage 2: FPS + ball on sampled coords
    k_fps<S1,S2><<<BB,256>>>((const float*)pnx1, (size_t)S1*3, 3, 1, (int*)pfps2, (float*)pnx2);
    k_ball<<<BB*S2/4,128>>>((const float*)pnx1, (size_t)S1*3, 3, 1, S1, (const float*)pnx2, S2, (int*)pgi2);

    // sg2
    k_sg_gather<256,256><<<BB*S2, 256, smA2>>>(wc, (const float*)pF1max, (size_t)S1*128, 128, 1,
        scl + 3*CMAX, bia + 3*CMAX, (const int*)pgi2, (const int*)pfps2, S2,
        (float*)pG2, psum + 4*NSLOT*CMAX, psq + 4*NSLOT*CMAX);
    k_fin<<<1,256>>>(psum + 4*NSLOT*CMAX, psq + 4*NSLOT*CMAX, scl + 4*CMAX, bia + 4*CMAX, 256, 1.0/((double)BB*S2*NS));
    k_sg_bngemm<256><<<BB*S2, 256, smB2>>>(wd, (const float*)pG2, scl + 4*CMAX, bia + 4*CMAX,
        (float*)pF2max, psum + 5*NSLOT*CMAX, psq + 5*NSLOT*CMAX);
    k_fin<<<1,256>>>(psum + 5*NSLOT*CMAX, psq + 5*NSLOT*CMAX, scl + 5*CMAX, bia + 5*CMAX, 256, 1.0/((double)BB*S2*NS));

    // outputs: coords then f2
    cudaMemcpyAsync(d_out, pnx2, (size_t)BB*S2*3*sizeof(float), cudaMemcpyDeviceToDevice, 0);
    k_out_f2<<<(BB*256*256)/256, 256>>>((const float*)pF2max, scl + 5*CMAX, bia + 5*CMAX, (float*)d_out);
}